// round 1
// baseline (speedup 1.0000x reference)
#include <cuda_runtime.h>
#include <math.h>

#define KE_KCAL 332.0636f

// ---------------- scratch (no allocations allowed) ----------------
struct Consts {
    float c[4], ex[4];
    float csum_inv, dinv;
};
__device__ Consts g_c;
__device__ float  g_zpow[128];          // z^z_exp lookup, z in [0,127]
__device__ int    g_prefix[1025];       // exclusive prefix of num_atoms (M<=1024)
__device__ float4 g_atoms[262144];      // packed per-atom: x,y,z, (z | mol<<8)
__device__ float  g_acc[1024 * 32];     // padded per-molecule accumulators

// ---------------- setup kernels ----------------
__global__ void k_init(const float* __restrict__ d_inv,
                       const float* __restrict__ ze_inv,
                       const float* __restrict__ c_inv,
                       const float* __restrict__ ex_inv) {
    __shared__ float s_zexp;
    int t = threadIdx.x;
    if (t == 0) {
        float d  = log1pf(expf(d_inv[0]));
        float ze = log1pf(expf(ze_inv[0]));
        s_zexp = ze;
        float csum = 0.f;
        #pragma unroll
        for (int k = 0; k < 4; k++) {
            float ck = log1pf(expf(c_inv[k]));
            float ek = log1pf(expf(ex_inv[k]));
            g_c.c[k] = ck; g_c.ex[k] = ek;
            csum += ck;
        }
        g_c.csum_inv = 1.f / csum;
        g_c.dinv     = 1.f / d;
    }
    __syncthreads();
    float ze = s_zexp;
    if (t < 128) {
        g_zpow[t] = (t == 0) ? 0.f : powf((float)t, ze);
    }
}

__global__ void k_scan(const int* __restrict__ na, int M) {
    __shared__ int s[1024];
    int t = threadIdx.x;
    int v = (t < M) ? na[t] : 0;
    s[t] = v;
    __syncthreads();
    for (int o = 1; o < 1024; o <<= 1) {
        int x = (t >= o) ? s[t - o] : 0;
        __syncthreads();
        s[t] += x;
        __syncthreads();
    }
    if (t == 0) g_prefix[0] = 0;
    if (t < M) g_prefix[t + 1] = s[t];
}

__global__ void k_zero_acc() {
    int t = blockIdx.x * blockDim.x + threadIdx.x;
    if (t < 1024 * 32) g_acc[t] = 0.f;
}

__global__ void k_atoms(const float* __restrict__ xyz,
                        const int*   __restrict__ z,
                        int N, int M) {
    int a = blockIdx.x * blockDim.x + threadIdx.x;
    if (a >= N) return;
    // binary search: largest m with prefix[m] <= a
    int lo = 0, hi = M;
    while (hi - lo > 1) {
        int mid = (lo + hi) >> 1;
        if (g_prefix[mid] <= a) lo = mid; else hi = mid;
    }
    float4 v;
    v.x = xyz[3 * a];
    v.y = xyz[3 * a + 1];
    v.z = xyz[3 * a + 2];
    v.w = __int_as_float((z[a] & 255) | (lo << 8));
    g_atoms[a] = v;
}

// ---------------- main edge kernel ----------------
__global__ void __launch_bounds__(256)
k_edges(const int2* __restrict__ nb, const float* __restrict__ off, int E) {
    const float c0 = g_c.c[0],  c1 = g_c.c[1],  c2 = g_c.c[2],  c3 = g_c.c[3];
    const float e0 = g_c.ex[0], e1 = g_c.ex[1], e2 = g_c.ex[2], e3 = g_c.ex[3];
    const float csi  = g_c.csum_inv;
    const float dinv = g_c.dinv;
    const int slot = threadIdx.x & 31;

    int stride = gridDim.x * blockDim.x;
    for (int e = blockIdx.x * blockDim.x + threadIdx.x; e < E; e += stride) {
        int2 p = nb[e];
        int i = p.x, j = p.y;
        if (j <= i) continue;                      // mask: j > i only

        float4 ai = g_atoms[i];
        float4 aj = g_atoms[j];
        float dx = ai.x - aj.x - off[3 * e];
        float dy = ai.y - aj.y - off[3 * e + 1];
        float dz = ai.z - aj.z - off[3 * e + 2];
        float d2 = fmaf(dx, dx, fmaf(dy, dy, dz * dz)) + 3e-15f;
        if (d2 >= 25.f) continue;                  // f_cut == 0 beyond R_CUT

        float rinv = rsqrtf(d2);
        float r    = d2 * rinv;

        int wi = __float_as_int(ai.w);
        int wj = __float_as_int(aj.w);
        float zp = __ldg(&g_zpow[wi & 255]) + __ldg(&g_zpow[wj & 255]);
        float t  = -r * zp * dinv;                 // -r / a

        float phi = fmaf(c0, __expf(e0 * t),
                    fmaf(c1, __expf(e1 * t),
                    fmaf(c2, __expf(e2 * t),
                         c3 * __expf(e3 * t))));

        float fcut = __expf(-d2 * __frcp_rn(25.f - d2));

        float zi = (float)(wi & 255);
        float zj = (float)(wj & 255);
        float pair = KE_KCAL * zi * zj * rinv * phi * csi * fcut;

        int mol = wi >> 8;
        atomicAdd(&g_acc[(mol << 5) + slot], pair);
    }
}

__global__ void k_reduce(float* __restrict__ out, int M) {
    int m = blockIdx.x * blockDim.x + threadIdx.x;
    if (m >= M) return;
    float s = 0.f;
    #pragma unroll
    for (int k = 0; k < 32; k++) s += g_acc[(m << 5) + k];
    out[m] = s;
}

// ---------------- launch ----------------
extern "C" void kernel_launch(void* const* d_in, const int* in_sizes, int n_in,
                              void* d_out, int out_size) {
    const float* xyz    = (const float*)d_in[0];
    const int*   z      = (const int*)  d_in[1];
    const int*   nbrs   = (const int*)  d_in[2];
    const int*   natoms = (const int*)  d_in[3];
    const float* off    = (const float*)d_in[4];
    const float* d_inv  = (const float*)d_in[5];
    const float* ze_inv = (const float*)d_in[6];
    const float* c_inv  = (const float*)d_in[7];
    const float* ex_inv = (const float*)d_in[8];

    int N = in_sizes[1];
    int E = in_sizes[2] / 2;
    int M = in_sizes[3];
    float* out = (float*)d_out;

    k_init<<<1, 128>>>(d_inv, ze_inv, c_inv, ex_inv);
    k_scan<<<1, 1024>>>(natoms, M);
    k_zero_acc<<<(1024 * 32) / 256, 256>>>();
    k_atoms<<<(N + 255) / 256, 256>>>(xyz, z, N, M);
    k_edges<<<1184, 256>>>((const int2*)nbrs, off, E);
    k_reduce<<<(M + 127) / 128, 128>>>(out, M);
}

// round 2
// speedup vs baseline: 1.0383x; 1.0383x over previous
#include <cuda_runtime.h>
#include <math.h>

#define KE_KCAL 332.0636f

// ---------------- scratch (no allocations allowed) ----------------
struct Consts {
    float c[4], ex[4];
    float csum_inv, dinv;
};
__device__ Consts g_c;
__device__ float  g_zpow[128];          // z^z_exp lookup, z in [0,127]
__device__ int    g_prefix[1026];       // exclusive prefix of num_atoms (M<=1024)
__device__ float4 g_atoms[262144];      // packed per-atom: x,y,z, (z | mol<<8)
__device__ float  g_acc[1024 * 32];     // padded per-molecule accumulators

// ---------------- setup: consts + zpow + prefix scan, one launch ----------------
__global__ void k_setup(const float* __restrict__ d_inv,
                        const float* __restrict__ ze_inv,
                        const float* __restrict__ c_inv,
                        const float* __restrict__ ex_inv,
                        const int*   __restrict__ na, int M) {
    __shared__ float s_zexp;
    __shared__ int s[1024];
    int t = threadIdx.x;
    if (t == 0) {
        float d  = log1pf(expf(d_inv[0]));
        float ze = log1pf(expf(ze_inv[0]));
        s_zexp = ze;
        float csum = 0.f;
        #pragma unroll
        for (int k = 0; k < 4; k++) {
            float ck = log1pf(expf(c_inv[k]));
            float ek = log1pf(expf(ex_inv[k]));
            g_c.c[k] = ck; g_c.ex[k] = ek;
            csum += ck;
        }
        g_c.csum_inv = 1.f / csum;
        g_c.dinv     = 1.f / d;
    }
    // inclusive scan of num_atoms
    int v = (t < M) ? na[t] : 0;
    s[t] = v;
    __syncthreads();
    float ze = s_zexp;
    if (t < 128) g_zpow[t] = (t == 0) ? 0.f : powf((float)t, ze);
    for (int o = 1; o < 1024; o <<= 1) {
        int x = (t >= o) ? s[t - o] : 0;
        __syncthreads();
        s[t] += x;
        __syncthreads();
    }
    if (t == 0) { g_prefix[0] = 0; g_prefix[M + 1] = 0x7fffffff; }
    if (t < M) g_prefix[t + 1] = s[t];
}

// ---------------- atom packing (4 atoms/thread) + acc zeroing ----------------
__global__ void __launch_bounds__(256)
k_atoms(const float* __restrict__ xyz,
        const int*   __restrict__ z,
        int N, int M) {
    __shared__ int sp[1026];
    int t = threadIdx.x;
    for (int k = t; k <= M + 1; k += blockDim.x) sp[k] = g_prefix[k];
    __syncthreads();

    int gtid = blockIdx.x * blockDim.x + t;

    // zero accumulators (first 2048 threads, float4 stores)
    if (gtid < 2048) {
        float4 zv = make_float4(0.f, 0.f, 0.f, 0.f);
        #pragma unroll
        for (int k = 0; k < 4; k++)
            ((float4*)g_acc)[gtid + k * 2048] = zv;
    }

    int base = gtid * 4;
    if (base >= N) return;

    // one binary search for the group, then linear advance
    int lo = 0, hi = M;
    while (hi - lo > 1) {
        int mid = (lo + hi) >> 1;
        if (sp[mid] <= base) lo = mid; else hi = mid;
    }

    if (base + 4 <= N) {
        const float4* x4 = (const float4*)(xyz + base * 3);
        float4 p0 = x4[0], p1 = x4[1], p2 = x4[2];
        int4 zz = *(const int4*)(z + base);
        float xs[4] = {p0.x, p0.w, p1.z, p2.y};
        float ys[4] = {p0.y, p1.x, p1.w, p2.z};
        float zs[4] = {p0.z, p1.y, p2.x, p2.w};
        int   zi[4] = {zz.x, zz.y, zz.z, zz.w};
        #pragma unroll
        for (int k = 0; k < 4; k++) {
            int a = base + k;
            while (sp[lo + 1] <= a) lo++;
            float4 v;
            v.x = xs[k]; v.y = ys[k]; v.z = zs[k];
            v.w = __int_as_float((zi[k] & 255) | (lo << 8));
            g_atoms[a] = v;
        }
    } else {
        for (int a = base; a < N; a++) {
            while (sp[lo + 1] <= a) lo++;
            float4 v;
            v.x = xyz[3 * a]; v.y = xyz[3 * a + 1]; v.z = xyz[3 * a + 2];
            v.w = __int_as_float((z[a] & 255) | (lo << 8));
            g_atoms[a] = v;
        }
    }
}

// ---------------- main edge kernel: 4 edges/thread, vectorized ----------------
__global__ void __launch_bounds__(256)
k_edges(const int4* __restrict__ nb4, const float4* __restrict__ off4,
        const int2* __restrict__ nb, const float* __restrict__ off, int E) {
    __shared__ float s_zpow[128];
    if (threadIdx.x < 128) s_zpow[threadIdx.x] = g_zpow[threadIdx.x];
    __syncthreads();

    const float c0 = g_c.c[0],  c1 = g_c.c[1],  c2 = g_c.c[2],  c3 = g_c.c[3];
    const float e0 = g_c.ex[0], e1 = g_c.ex[1], e2 = g_c.ex[2], e3 = g_c.ex[3];
    const float csi  = g_c.csum_inv;
    const float dinv = g_c.dinv;
    const int slot = threadIdx.x & 31;

    auto body = [&](int i, int j, float ox, float oy, float oz) {
        if (j <= i) return;
        float4 ai = g_atoms[i];
        float4 aj = g_atoms[j];
        float dx = ai.x - aj.x - ox;
        float dy = ai.y - aj.y - oy;
        float dz = ai.z - aj.z - oz;
        float d2 = fmaf(dx, dx, fmaf(dy, dy, dz * dz)) + 3e-15f;
        if (d2 >= 25.f) return;
        float rinv = rsqrtf(d2);
        float r    = d2 * rinv;
        int wi = __float_as_int(ai.w);
        int wj = __float_as_int(aj.w);
        float zp = s_zpow[wi & 255] + s_zpow[wj & 255];
        float tt = -r * zp * dinv;
        float phi = fmaf(c0, __expf(e0 * tt),
                    fmaf(c1, __expf(e1 * tt),
                    fmaf(c2, __expf(e2 * tt),
                         c3 * __expf(e3 * tt))));
        float fcut = __expf(-d2 * __frcp_rn(25.f - d2));
        float zi = (float)(wi & 255);
        float zj = (float)(wj & 255);
        float pair = KE_KCAL * zi * zj * rinv * phi * csi * fcut;
        atomicAdd(&g_acc[((wi >> 8) << 5) + slot], pair);
    };

    int t = blockIdx.x * blockDim.x + threadIdx.x;
    int G = E >> 2;            // groups of 4 edges
    if (t < G) {
        int4 n01 = nb4[2 * t];
        int4 n23 = nb4[2 * t + 1];
        float4 o0 = off4[3 * t];
        float4 o1 = off4[3 * t + 1];
        float4 o2 = off4[3 * t + 2];
        body(n01.x, n01.y, o0.x, o0.y, o0.z);
        body(n01.z, n01.w, o0.w, o1.x, o1.y);
        body(n23.x, n23.y, o1.z, o1.w, o2.x);
        body(n23.z, n23.w, o2.y, o2.z, o2.w);
    }
    // tail (E % 4 edges) handled by thread 0 of block 0
    if (t == 0) {
        for (int e = G * 4; e < E; e++) {
            int2 p = nb[e];
            body(p.x, p.y, off[3 * e], off[3 * e + 1], off[3 * e + 2]);
        }
    }
}

__global__ void k_reduce(float* __restrict__ out, int M) {
    int m = blockIdx.x * blockDim.x + threadIdx.x;
    if (m >= M) return;
    float s = 0.f;
    const float4* a4 = (const float4*)&g_acc[m << 5];
    #pragma unroll
    for (int k = 0; k < 8; k++) {
        float4 v = a4[k];
        s += v.x + v.y + v.z + v.w;
    }
    out[m] = s;
}

// ---------------- launch ----------------
extern "C" void kernel_launch(void* const* d_in, const int* in_sizes, int n_in,
                              void* d_out, int out_size) {
    const float* xyz    = (const float*)d_in[0];
    const int*   z      = (const int*)  d_in[1];
    const int*   nbrs   = (const int*)  d_in[2];
    const int*   natoms = (const int*)  d_in[3];
    const float* off    = (const float*)d_in[4];
    const float* d_inv  = (const float*)d_in[5];
    const float* ze_inv = (const float*)d_in[6];
    const float* c_inv  = (const float*)d_in[7];
    const float* ex_inv = (const float*)d_in[8];

    int N = in_sizes[1];
    int E = in_sizes[2] / 2;
    int M = in_sizes[3];
    float* out = (float*)d_out;

    k_setup<<<1, 1024>>>(d_inv, ze_inv, c_inv, ex_inv, natoms, M);
    int atomThreads = (N + 3) / 4;
    k_atoms<<<(atomThreads + 255) / 256, 256>>>(xyz, z, N, M);
    int G = E / 4;
    k_edges<<<(G + 255) / 256, 256>>>((const int4*)nbrs, (const float4*)off,
                                      (const int2*)nbrs, off, E);
    k_reduce<<<(M + 127) / 128, 128>>>(out, M);
}